// round 2
// baseline (speedup 1.0000x reference)
#include <cuda_runtime.h>
#include <math.h>

#define HDIM 32
#define NDIM 1024
#define BATCH 8
#define NT 2048            // LUT resolution
#define TILE 32
#define TPAIRS 528         // 32*33/2 upper-triangular tile pairs
#define NPAIRS (BATCH * TPAIRS)

// LUT of the scalar MLP f(x) on [0,1], NT+1 samples.
__device__ float g_lut[NT + 1];

// ---------------------------------------------------------------------------
// Kernel 1: build the LUT. One MLP eval per thread (2049 evals total).
// ---------------------------------------------------------------------------
__global__ void build_lut_kernel(const float* __restrict__ w1,
                                 const float* __restrict__ b1,
                                 const float* __restrict__ w2,
                                 const float* __restrict__ b2,
                                 const float* __restrict__ w3,
                                 const float* __restrict__ b3) {
    __shared__ float sw2[HDIM * HDIM];
    __shared__ float sw1[HDIM], sb1[HDIM], sb2[HDIM], sw3[HDIM];
    __shared__ float sb3;
    const int tid = threadIdx.x;
    for (int i = tid; i < HDIM * HDIM; i += blockDim.x) sw2[i] = w2[i];
    if (tid < HDIM) {
        sw1[tid] = w1[tid];   // w1 shape (1,H) -> contiguous H floats
        sb1[tid] = b1[tid];
        sb2[tid] = b2[tid];
        sw3[tid] = w3[tid];   // w3 shape (H,1) -> contiguous H floats
    }
    if (tid == 0) sb3 = b3[0];
    __syncthreads();

    const int e = blockIdx.x * blockDim.x + tid;
    if (e > NT) return;
    const float x = (float)e * (1.0f / (float)NT);

    float h1[HDIM];
#pragma unroll
    for (int h = 0; h < HDIM; h++)
        h1[h] = fmaxf(fmaf(x, sw1[h], sb1[h]), 0.0f);

    float acc = sb3;
#pragma unroll 4
    for (int k = 0; k < HDIM; k++) {
        float s = sb2[k];
#pragma unroll
        for (int h = 0; h < HDIM; h++)
            s = fmaf(h1[h], sw2[h * HDIM + k], s);
        acc = fmaf(fmaxf(s, 0.0f), sw3[k], acc);
    }
    g_lut[e] = 1.0f / (1.0f + expf(-acc));
}

// ---------------------------------------------------------------------------
// LUT lookup with linear interpolation (x expected in [0,1)).
// ---------------------------------------------------------------------------
__device__ __forceinline__ float lut_lookup(const float* __restrict__ lut, float x) {
    float u = x * (float)NT;
    int i = (int)u;
    i = max(0, min(i, NT - 1));
    float f0 = lut[i];
    float f1 = lut[i + 1];
    return fmaf(u - (float)i, f1 - f0, f0);
}

// ---------------------------------------------------------------------------
// Kernel 2: main. Each block grid-strides over (batch, ti<=tj) tile pairs.
// Reads the (ti,tj) tile coalesced from gmem and the (tj,ti) tile coalesced
// into smem; computes val = pair ? 0.5*(f(x_ij)+f(x_ji)) : 0 with diagonal
// zeroing; writes both output tiles coalesced (transpose via padded smem).
// node_masks arrives as int32 (harness promotes jnp.bool_).
// ---------------------------------------------------------------------------
__global__ void __launch_bounds__(256)
corrector_kernel(const float* __restrict__ sim,
                 const int* __restrict__ masks,
                 float* __restrict__ out) {
    __shared__ float slut[NT + 1];              // 8196 B
    __shared__ float sBt[TILE][TILE + 1];       // transpose-source tile
    __shared__ float so[TILE][TILE + 1];        // output tile staged transposed
    __shared__ int smrow[TILE], smcol[TILE];

    const int tid = threadIdx.x;
    const int c = tid & 31;       // lane = column within tile
    const int w = tid >> 5;       // warp id 0..7 = base row

    for (int i = tid; i <= NT; i += 256) slut[i] = g_lut[i];

    for (int p = blockIdx.x; p < NPAIRS; p += gridDim.x) {
        int b = p / TPAIRS;
        int t = p - b * TPAIRS;
        // unrank triangular index -> (ti, tj), ti <= tj
        int ti = 0;
        while (t >= TILE - ti) { t -= TILE - ti; ti++; }
        const int tj = ti + t;

        const float* __restrict__ simb = sim + (size_t)b * NDIM * NDIM;

        __syncthreads();  // protect smem (lut on first iter, tiles on later)

        // coalesced load of the (tj,ti) tile
#pragma unroll
        for (int k = 0; k < 4; k++) {
            int r = w + 8 * k;
            sBt[r][c] = simb[(size_t)(tj * TILE + r) * NDIM + ti * TILE + c];
        }
        if (tid < TILE)            smrow[tid]        = masks[b * NDIM + ti * TILE + tid];
        else if (tid < 2 * TILE)   smcol[tid - TILE] = masks[b * NDIM + tj * TILE + (tid - TILE)];
        __syncthreads();

#pragma unroll
        for (int k = 0; k < 4; k++) {
            int r = w + 8 * k;
            int gi = ti * TILE + r;
            int gj = tj * TILE + c;
            float xA = simb[(size_t)gi * NDIM + gj];  // coalesced
            float xB = sBt[c][r];                     // padded smem, conflict-free
            float val = 0.0f;
            if ((smrow[r] != 0) && (smcol[c] != 0) && (gi != gj)) {
                val = 0.5f * (lut_lookup(slut, xA) + lut_lookup(slut, xB));
            }
            out[((size_t)b * NDIM + gi) * NDIM + gj] = val;  // coalesced
            so[c][r] = val;   // stride-33 scatter: conflict-free
        }

        if (ti != tj) {           // uniform branch across block
            __syncthreads();
#pragma unroll
            for (int k = 0; k < 4; k++) {
                int r = w + 8 * k;
                out[((size_t)b * NDIM + tj * TILE + r) * NDIM + ti * TILE + c] = so[r][c];
            }
        }
    }
}

// ---------------------------------------------------------------------------
// Harness entry
// ---------------------------------------------------------------------------
extern "C" void kernel_launch(void* const* d_in, const int* in_sizes, int n_in,
                              void* d_out, int out_size) {
    const float* sim   = (const float*)d_in[0];
    const int*   masks = (const int*)d_in[1];
    const float* w1    = (const float*)d_in[2];
    const float* b1    = (const float*)d_in[3];
    const float* w2    = (const float*)d_in[4];
    const float* b2    = (const float*)d_in[5];
    const float* w3    = (const float*)d_in[6];
    const float* b3    = (const float*)d_in[7];
    float* out = (float*)d_out;

    build_lut_kernel<<<(NT + 1 + 63) / 64, 64>>>(w1, b1, w2, b2, w3, b3);
    corrector_kernel<<<1056, 256>>>(sim, masks, out);
}

// round 3
// speedup vs baseline: 1.1145x; 1.1145x over previous
#include <cuda_runtime.h>
#include <math.h>

#define HDIM 32
#define NDIM 1024
#define BATCH 8
#define NT 512             // LUT resolution (err ~1e-6, budget 1e-3)
#define TILE 32
#define TPAIRS 528         // 32*33/2 upper-triangular tile pairs
#define NPAIRS (BATCH * TPAIRS)

// LUT entry i = (f(i/NT), f((i+1)/NT)) for fused interpolation with one LDS.64
__device__ float2 g_lut2[NT];

// ---------------------------------------------------------------------------
// Kernel 1: build LUT. One WARP per sample point e in [0, NT]:
// lane h computes hidden unit h of layer 1, shuffles broadcast for layer 2,
// warp-reduce for layer 3. 33 warps total -> sub-microsecond.
// ---------------------------------------------------------------------------
__global__ void build_lut_kernel(const float* __restrict__ w1,
                                 const float* __restrict__ b1,
                                 const float* __restrict__ w2,
                                 const float* __restrict__ b2,
                                 const float* __restrict__ w3,
                                 const float* __restrict__ b3) {
    const int gwarp = (blockIdx.x * blockDim.x + threadIdx.x) >> 5;
    const int lane  = threadIdx.x & 31;
    if (gwarp > NT) return;

    const float x = (float)gwarp * (1.0f / (float)NT);

    // layer 1: lane = hidden unit
    float h1 = fmaxf(fmaf(x, w1[lane], b1[lane]), 0.0f);

    // layer 2: lane = output unit k; gather h1 via shuffle
    float s = b2[lane];
#pragma unroll
    for (int h = 0; h < HDIM; h++) {
        float h1h = __shfl_sync(0xffffffffu, h1, h);
        s = fmaf(h1h, w2[h * HDIM + lane], s);
    }
    // layer 3 partial + warp reduction
    float part = fmaxf(s, 0.0f) * w3[lane];
#pragma unroll
    for (int off = 16; off > 0; off >>= 1)
        part += __shfl_xor_sync(0xffffffffu, part, off);

    if (lane == 0) {
        float f = 1.0f / (1.0f + expf(-(part + b3[0])));
        if (gwarp < NT) g_lut2[gwarp].x     = f;
        if (gwarp > 0)  g_lut2[gwarp - 1].y = f;
    }
}

// ---------------------------------------------------------------------------
// Fused LUT lookup: one LDS.64 + interp.
// ---------------------------------------------------------------------------
__device__ __forceinline__ float lutf(const float2* __restrict__ slut, float x) {
    float u = x * (float)NT;
    int i = (int)u;
    i = min(max(i, 0), NT - 1);
    float2 v = slut[i];
    return fmaf(u - (float)i, v.y - v.x, v.x);
}

// ---------------------------------------------------------------------------
// Kernel 2: main. Block grid-strides over (batch, ti<=tj) tile pairs.
// Thread (r = tid>>3, q = tid&7) owns row r, float4 column group q of the
// 32x32 tile. All smem transposes use the diagonal swizzle
//   elem(row,col) -> flat[row*32 + ((col+row)&31)]
// which is conflict-free for BOTH the row-major scatter and the transposed
// column gather.
// ---------------------------------------------------------------------------
__global__ void __launch_bounds__(256)
corrector_kernel(const float* __restrict__ sim,
                 const int* __restrict__ masks,
                 float* __restrict__ out) {
    __shared__ float2 slut[NT];          // 4 KB
    __shared__ float  sBt[TILE * TILE];  // swizzled B tile (transpose source)
    __shared__ float  sO [TILE * TILE];  // swizzled output tile (mirror stage)
    __shared__ int    smrow[TILE], smcol[TILE];

    const int tid = threadIdx.x;
    const int r   = tid >> 3;       // 0..31 tile row
    const int q   = tid & 7;        // 0..7  float4 col group
    const int c0  = 4 * q;

    for (int i = tid; i < NT; i += 256) slut[i] = g_lut2[i];

    for (int p = blockIdx.x; p < NPAIRS; p += gridDim.x) {
        const int b = p / TPAIRS;
        int t = p - b * TPAIRS;
        // closed-form triangular unrank: offset(ti) = ti*(65-ti)/2
        int ti = (int)(0.5f * (65.0f - sqrtf(4225.0f - 8.0f * (float)t)));
        ti = min(max(ti, 0), 31);
        while (ti < 31 && (ti + 1) * (65 - (ti + 1)) / 2 <= t) ti++;
        while (ti > 0  && ti * (65 - ti) / 2 > t) ti--;
        const int tj = ti + (t - ti * (65 - ti) / 2);

        const float* __restrict__ simb = sim + (size_t)b * (NDIM * NDIM);
        float*       __restrict__ outb = out + (size_t)b * (NDIM * NDIM);

        __syncthreads();  // protect smem reads of previous iteration (and slut fill)

        // B tile (tj,ti): coalesced float4 load, swizzled scalar scatter
        float4 b4 = *(const float4*)(simb + (size_t)(tj * TILE + r) * NDIM + ti * TILE + c0);
        sBt[r * 32 + ((c0 + 0 + r) & 31)] = b4.x;
        sBt[r * 32 + ((c0 + 1 + r) & 31)] = b4.y;
        sBt[r * 32 + ((c0 + 2 + r) & 31)] = b4.z;
        sBt[r * 32 + ((c0 + 3 + r) & 31)] = b4.w;
        if (tid < TILE)          smrow[tid]      = masks[b * NDIM + ti * TILE + tid];
        else if (tid < 2 * TILE) smcol[tid - 32] = masks[b * NDIM + tj * TILE + (tid - 32)];

        // A tile (ti,tj): coalesced float4 load (overlaps the barrier wait)
        float4 a4 = *(const float4*)(simb + (size_t)(ti * TILE + r) * NDIM + tj * TILE + c0);
        __syncthreads();

        // transposed gather: xB_k = B[c0+k][r]
        float xB0 = sBt[(c0 + 0) * 32 + ((r + c0 + 0) & 31)];
        float xB1 = sBt[(c0 + 1) * 32 + ((r + c0 + 1) & 31)];
        float xB2 = sBt[(c0 + 2) * 32 + ((r + c0 + 2) & 31)];
        float xB3 = sBt[(c0 + 3) * 32 + ((r + c0 + 3) & 31)];

        // 8 independent lookups (ILP hides LDS latency)
        float fA0 = lutf(slut, a4.x), fA1 = lutf(slut, a4.y);
        float fA2 = lutf(slut, a4.z), fA3 = lutf(slut, a4.w);
        float fB0 = lutf(slut, xB0), fB1 = lutf(slut, xB1);
        float fB2 = lutf(slut, xB2), fB3 = lutf(slut, xB3);

        const int  mr   = smrow[r];
        const int  gi   = ti * TILE + r;
        const int  gjb  = tj * TILE + c0;
        float4 v;
        v.x = (mr && smcol[c0 + 0] && gi != gjb + 0) ? 0.5f * (fA0 + fB0) : 0.0f;
        v.y = (mr && smcol[c0 + 1] && gi != gjb + 1) ? 0.5f * (fA1 + fB1) : 0.0f;
        v.z = (mr && smcol[c0 + 2] && gi != gjb + 2) ? 0.5f * (fA2 + fB2) : 0.0f;
        v.w = (mr && smcol[c0 + 3] && gi != gjb + 3) ? 0.5f * (fA3 + fB3) : 0.0f;

        // forward tile: coalesced float4 store
        *(float4*)(outb + (size_t)gi * NDIM + gjb) = v;

        if (ti != tj) {  // uniform branch
            // stage swizzled, then emit the mirror tile coalesced
            sO[r * 32 + ((c0 + 0 + r) & 31)] = v.x;
            sO[r * 32 + ((c0 + 1 + r) & 31)] = v.y;
            sO[r * 32 + ((c0 + 2 + r) & 31)] = v.z;
            sO[r * 32 + ((c0 + 3 + r) & 31)] = v.w;
            __syncthreads();
            float4 m;
            m.x = sO[(c0 + 0) * 32 + ((r + c0 + 0) & 31)];
            m.y = sO[(c0 + 1) * 32 + ((r + c0 + 1) & 31)];
            m.z = sO[(c0 + 2) * 32 + ((r + c0 + 2) & 31)];
            m.w = sO[(c0 + 3) * 32 + ((r + c0 + 3) & 31)];
            *(float4*)(outb + (size_t)(tj * TILE + r) * NDIM + ti * TILE + c0) = m;
        }
    }
}

// ---------------------------------------------------------------------------
// Harness entry
// ---------------------------------------------------------------------------
extern "C" void kernel_launch(void* const* d_in, const int* in_sizes, int n_in,
                              void* d_out, int out_size) {
    const float* sim   = (const float*)d_in[0];
    const int*   masks = (const int*)d_in[1];
    const float* w1    = (const float*)d_in[2];
    const float* b1    = (const float*)d_in[3];
    const float* w2    = (const float*)d_in[4];
    const float* b2    = (const float*)d_in[5];
    const float* w3    = (const float*)d_in[6];
    const float* b3    = (const float*)d_in[7];
    float* out = (float*)d_out;

    // (NT+1)=513 warps -> 129 blocks of 128 threads (4 warps each)
    build_lut_kernel<<<129, 128>>>(w1, b1, w2, b2, w3, b3);
    corrector_kernel<<<1056, 256>>>(sim, masks, out);
}